// round 1
// baseline (speedup 1.0000x reference)
#include <cuda_runtime.h>

#define N_NODES 50000
#define N_EDGES 200000
#define IN_F 32
#define HID 32
#define N_GRAPHS 64
#define TILE_E 256

// ---------------- scratch (no allocs allowed) ----------------
__device__ float g_agg[N_NODES * HID];
__device__ float g_cnt[N_NODES];
__device__ float g_gsum[N_GRAPHS * HID];
__device__ float g_gcnt[N_GRAPHS];

__device__ __forceinline__ unsigned f2tf32(float f) {
    unsigned r;
    asm("cvt.rna.tf32.f32 %0, %1;" : "=r"(r) : "f"(f));
    return r;
}

#define MMA_TF32(C, A, B0, B1)                                                  \
    asm volatile("mma.sync.aligned.m16n8k8.row.col.f32.tf32.tf32.f32 "          \
                 "{%0,%1,%2,%3}, {%4,%5,%6,%7}, {%8,%9}, {%0,%1,%2,%3};"        \
                 : "+f"((C)[0]), "+f"((C)[1]), "+f"((C)[2]), "+f"((C)[3])       \
                 : "r"((A)[0]), "r"((A)[1]), "r"((A)[2]), "r"((A)[3]),          \
                   "r"(B0), "r"(B1))

// ---------------- K0: zero scratch ----------------
__global__ void zero_kernel() {
    int idx = blockIdx.x * blockDim.x + threadIdx.x;
    int stride = gridDim.x * blockDim.x;
    for (int i = idx; i < N_NODES * HID; i += stride) g_agg[i] = 0.f;
    for (int i = idx; i < N_NODES; i += stride) g_cnt[i] = 0.f;
    if (idx < N_GRAPHS * HID) g_gsum[idx] = 0.f;
    if (idx < N_GRAPHS) g_gcnt[idx] = 0.f;
}

// ---------------- K1: edge messages (the GEMM) ----------------
// msg[e, n] = sum_k G[e,k] * W2r[k,n],  G[e, j*32+i] = h(e,j)*x[src[e], i]
// K = 65*32 (last j-slab = bias with h == 1).
__global__ void __launch_bounds__(256) edge_kernel(
    const float* __restrict__ x, const int* __restrict__ ei,
    const float* __restrict__ ea,
    const float* __restrict__ w1g, const float* __restrict__ b1g,
    const float* __restrict__ w2, const float* __restrict__ b2)
{
    __shared__ unsigned w2_sm[4096];   // 16 KB: chunk of 4 j-slabs (128 k-rows x 32 n), swizzled
    __shared__ float w1_sm[64], b1_sm[64];

    const int tid  = threadIdx.x;
    const int lane = tid & 31;
    const int wrp  = tid >> 5;
    const int e0   = blockIdx.x * TILE_E;

    if (tid < 64) { w1_sm[tid] = w1g[tid]; b1_sm[tid] = b1g[tid]; }

    const int r0 = lane >> 2;      // 0..7
    const int c0 = lane & 3;       // 0..3

    // 4 edge rows (2 m16 tiles) per thread
    int   erow[4];
    erow[0] = wrp * 32 + r0; erow[1] = erow[0] + 8;
    erow[2] = erow[0] + 16;  erow[3] = erow[0] + 24;

    int   dstv[4];
    bool  val[4];
    float av[4];
    float xp[4][8];

    #pragma unroll
    for (int t = 0; t < 4; t++) {
        int eg = e0 + erow[t];
        val[t] = (eg < N_EDGES);
        int s  = val[t] ? ei[eg] : 0;
        dstv[t] = val[t] ? ei[N_EDGES + eg] : 0;
        av[t]   = val[t] ? ea[eg] : 0.f;
        const float* xr = x + s * IN_F;
        #pragma unroll
        for (int q = 0; q < 8; q++)
            xp[t][q] = val[t] ? xr[c0 + 4 * q] : 0.f;
    }

    // degree counts: exactly once per edge
    if (c0 == 0) {
        #pragma unroll
        for (int t = 0; t < 4; t++)
            if (val[t]) atomicAdd(&g_cnt[dstv[t]], 1.f);
    }

    float acc[2][4][4];
    #pragma unroll
    for (int a = 0; a < 2; a++)
        #pragma unroll
        for (int b = 0; b < 4; b++)
            #pragma unroll
            for (int c = 0; c < 4; c++) acc[a][b][c] = 0.f;

    for (int jc = 0; jc < 17; jc++) {
        __syncthreads();
        if (jc < 16) {
            const float4* srcp = (const float4*)(w2 + jc * 4096);
            #pragma unroll
            for (int k = 0; k < 4; k++) {
                int f = tid + k * 256;            // 0..1023 float4s
                int kr = f >> 3;
                int n4 = (f & 7) << 2;
                float4 v4 = srcp[f];
                unsigned* p = &w2_sm[kr * 32 + (n4 ^ ((kr & 3) << 3))];
                p[0] = f2tf32(v4.x); p[1] = f2tf32(v4.y);
                p[2] = f2tf32(v4.z); p[3] = f2tf32(v4.w);
            }
        } else {
            // bias slab: 1024 floats = 256 float4s (one per thread), rows 0..31 used
            const float4* srcp = (const float4*)b2;
            int f = tid;
            int kr = f >> 3;
            int n4 = (f & 7) << 2;
            float4 v4 = srcp[f];
            unsigned* p = &w2_sm[kr * 32 + (n4 ^ ((kr & 3) << 3))];
            p[0] = f2tf32(v4.x); p[1] = f2tf32(v4.y);
            p[2] = f2tf32(v4.z); p[3] = f2tf32(v4.w);
        }
        __syncthreads();

        const int njj = (jc < 16) ? 4 : 1;
        for (int jj = 0; jj < njj; jj++) {
            float h[4];
            if (jc < 16) {
                int j = jc * 4 + jj;
                float wj = w1_sm[j], bj = b1_sm[j];
                #pragma unroll
                for (int t = 0; t < 4; t++)
                    h[t] = fmaxf(fmaf(av[t], wj, bj), 0.f);
            } else {
                h[0] = h[1] = h[2] = h[3] = 1.f;
            }
            #pragma unroll
            for (int ic = 0; ic < 4; ic++) {
                unsigned arA[4], arB[4];
                arA[0] = f2tf32(h[0] * xp[0][2 * ic]);
                arA[1] = f2tf32(h[1] * xp[1][2 * ic]);
                arA[2] = f2tf32(h[0] * xp[0][2 * ic + 1]);
                arA[3] = f2tf32(h[1] * xp[1][2 * ic + 1]);
                arB[0] = f2tf32(h[2] * xp[2][2 * ic]);
                arB[1] = f2tf32(h[3] * xp[3][2 * ic]);
                arB[2] = f2tf32(h[2] * xp[2][2 * ic + 1]);
                arB[3] = f2tf32(h[3] * xp[3][2 * ic + 1]);
                const int row0 = jj * 32 + ic * 8 + c0;
                #pragma unroll
                for (int nb = 0; nb < 4; nb++) {
                    int colsw = (nb * 8 + r0) ^ (c0 << 3);
                    unsigned bb0 = w2_sm[row0 * 32 + colsw];
                    unsigned bb1 = w2_sm[(row0 + 4) * 32 + colsw];
                    MMA_TF32(acc[0][nb], arA, bb0, bb1);
                    MMA_TF32(acc[1][nb], arB, bb0, bb1);
                }
            }
        }
    }

    // scatter messages (segment-sum by dst)
    #pragma unroll
    for (int tt = 0; tt < 2; tt++) {
        int t0 = tt * 2, t1 = tt * 2 + 1;
        #pragma unroll
        for (int nb = 0; nb < 4; nb++) {
            int n = nb * 8 + 2 * c0;
            if (val[t0]) {
                atomicAdd(&g_agg[dstv[t0] * HID + n],     acc[tt][nb][0]);
                atomicAdd(&g_agg[dstv[t0] * HID + n + 1], acc[tt][nb][1]);
            }
            if (val[t1]) {
                atomicAdd(&g_agg[dstv[t1] * HID + n],     acc[tt][nb][2]);
                atomicAdd(&g_agg[dstv[t1] * HID + n + 1], acc[tt][nb][3]);
            }
        }
    }
}

// ---------------- K2: node update + graph pooling ----------------
__global__ void __launch_bounds__(256) node_kernel(
    const float* __restrict__ x, const int* __restrict__ batch,
    const float* __restrict__ root, const float* __restrict__ conv_bias)
{
    int wrp = threadIdx.x >> 5, lane = threadIdx.x & 31;
    int n = blockIdx.x * 8 + wrp;
    if (n >= N_NODES) return;
    float v = g_agg[n * HID + lane];
    float c = g_cnt[n];
    v /= fmaxf(c, 1.f);
    float xv = x[n * IN_F + lane];
    float s = 0.f;
    #pragma unroll
    for (int i = 0; i < IN_F; i++) {
        float xi = __shfl_sync(0xffffffffu, xv, i);
        s = fmaf(xi, root[i * HID + lane], s);
    }
    v = fmaxf(v + s + conv_bias[lane], 0.f);
    int g = batch[n];
    atomicAdd(&g_gsum[g * HID + lane], v);
    if (lane == 0) atomicAdd(&g_gcnt[g], 1.f);
}

// ---------------- K3: classifier ----------------
__global__ void final_kernel(const float* __restrict__ lin_w,
                             const float* __restrict__ lin_b,
                             float* __restrict__ out)
{
    int t = threadIdx.x;
    if (t >= N_GRAPHS * 2) return;
    int g = t >> 1, c = t & 1;
    float cnt = fmaxf(g_gcnt[g], 1.f);
    float s = 0.f;
    #pragma unroll
    for (int h = 0; h < HID; h++)
        s += g_gsum[g * HID + h] * lin_w[h * 2 + c];
    out[g * 2 + c] = s / cnt + lin_b[c];
}

// ---------------- launcher ----------------
extern "C" void kernel_launch(void* const* d_in, const int* in_sizes, int n_in,
                              void* d_out, int out_size) {
    const float* x    = (const float*)d_in[0];
    const int*   ei   = (const int*)  d_in[1];
    const float* ea   = (const float*)d_in[2];
    const int*   bat  = (const int*)  d_in[3];
    const float* w1   = (const float*)d_in[4];
    const float* b1   = (const float*)d_in[5];
    const float* w2   = (const float*)d_in[6];
    const float* b2   = (const float*)d_in[7];
    const float* root = (const float*)d_in[8];
    const float* cb   = (const float*)d_in[9];
    const float* lw   = (const float*)d_in[10];
    const float* lb   = (const float*)d_in[11];
    float* out = (float*)d_out;

    zero_kernel<<<512, 256>>>();
    edge_kernel<<<(N_EDGES + TILE_E - 1) / TILE_E, 256>>>(x, ei, ea, w1, b1, w2, b2);
    node_kernel<<<(N_NODES + 7) / 8, 256>>>(x, bat, root, cb);
    final_kernel<<<1, 128>>>(lw, lb, out);
}